// round 3
// baseline (speedup 1.0000x reference)
#include <cuda_runtime.h>
#include <cuda_bf16.h>
#include <cstdint>
#include <cstddef>

// Problem dims
#define B_   128
#define S_   512
#define E_   256
#define H_   256
#define G4_  1024   // 4*H
#define A_   128
#define C_   2

// ---------------- scratch (device globals; no allocation allowed) ----------------
__device__ float g_xp[(size_t)S_ * B_ * G4_];   // [s][b][g]  x_proj + bias   (268 MB)
__device__ float g_h [(size_t)S_ * B_ * H_];    // [s][b][h]  LSTM hidden seq (67 MB)
__device__ float g_alpha[B_ * S_];              // scores -> softmax in place
__device__ unsigned g_bar;                      // monotone grid-barrier counter

// =====================================================================
// k1: x_proj = gather(emb, x) @ W_ih^T + (b_ih + b_hh), written [s][b][g]
// Tile: BM=128 (rows=(b,s)), BN=64 (gate cols), BK=16. 256 thr, 8x4/thread.
// =====================================================================
#define K1_BM 128
#define K1_BN 64
#define K1_BK 16
#define K1_AS 136   // As row stride (floats), multiple of 4
#define K1_BS 72    // Bs row stride

__global__ __launch_bounds__(256) void k1_xproj(
    const int* __restrict__ x, const float* __restrict__ emb,
    const float* __restrict__ W_ih, const float* __restrict__ b_ih,
    const float* __restrict__ b_hh)
{
    __shared__ __align__(16) float As[K1_BK * K1_AS];
    __shared__ __align__(16) float Bs[K1_BK * K1_BS];
    __shared__ int tok[K1_BM];

    const int t  = threadIdx.x;
    const int r0 = blockIdx.y * K1_BM;
    const int n0 = blockIdx.x * K1_BN;
    const int tm = t & 15;          // 16 row-threads
    const int tn = t >> 4;          // 16 col-threads

    if (t < K1_BM) tok[t] = x[r0 + t];

    float4 bias;
    {
        const float* bi = b_ih + n0 + tn * 4;
        const float* bh = b_hh + n0 + tn * 4;
        bias.x = bi[0] + bh[0]; bias.y = bi[1] + bh[1];
        bias.z = bi[2] + bh[2]; bias.w = bi[3] + bh[3];
    }

    float acc[8][4];
    #pragma unroll
    for (int i = 0; i < 8; i++)
        #pragma unroll
        for (int j = 0; j < 4; j++) acc[i][j] = 0.f;

    const int la_m  = t >> 2;   // 0..63 (two rows each: +0, +64)
    const int la_k4 = t & 3;
    const int lb_n  = t >> 2;   // 0..63
    const int lb_k4 = t & 3;

    __syncthreads();

    for (int bk = 0; bk < E_; bk += K1_BK) {
        const int bk4 = bk >> 2;
        // load A tile (gathered embedding rows), store transposed As[k][m]
        #pragma unroll
        for (int i = 0; i < 2; i++) {
            const int m = la_m + i * 64;
            float4 v = ((const float4*)emb)[(size_t)tok[m] * 64 + bk4 + la_k4];
            As[(la_k4 * 4 + 0) * K1_AS + m] = v.x;
            As[(la_k4 * 4 + 1) * K1_AS + m] = v.y;
            As[(la_k4 * 4 + 2) * K1_AS + m] = v.z;
            As[(la_k4 * 4 + 3) * K1_AS + m] = v.w;
        }
        // load B tile (W_ih rows), store transposed Bs[k][n]
        {
            float4 v = ((const float4*)W_ih)[(size_t)(n0 + lb_n) * 64 + bk4 + lb_k4];
            Bs[(lb_k4 * 4 + 0) * K1_BS + lb_n] = v.x;
            Bs[(lb_k4 * 4 + 1) * K1_BS + lb_n] = v.y;
            Bs[(lb_k4 * 4 + 2) * K1_BS + lb_n] = v.z;
            Bs[(lb_k4 * 4 + 3) * K1_BS + lb_n] = v.w;
        }
        __syncthreads();
        #pragma unroll
        for (int k = 0; k < K1_BK; k++) {
            float4 a0 = *(const float4*)&As[k * K1_AS + tm * 8];
            float4 a1 = *(const float4*)&As[k * K1_AS + tm * 8 + 4];
            float4 b4 = *(const float4*)&Bs[k * K1_BS + tn * 4];
            float av[8] = {a0.x,a0.y,a0.z,a0.w,a1.x,a1.y,a1.z,a1.w};
            float bv[4] = {b4.x,b4.y,b4.z,b4.w};
            #pragma unroll
            for (int i = 0; i < 8; i++)
                #pragma unroll
                for (int j = 0; j < 4; j++)
                    acc[i][j] = fmaf(av[i], bv[j], acc[i][j]);
        }
        __syncthreads();
    }

    // epilogue: write to [s][b][g]
    #pragma unroll
    for (int i = 0; i < 8; i++) {
        const int r  = r0 + tm * 8 + i;
        const int bb = r >> 9;          // r = b*S + s
        const int ss = r & (S_ - 1);
        float4 v;
        v.x = acc[i][0] + bias.x; v.y = acc[i][1] + bias.y;
        v.z = acc[i][2] + bias.z; v.w = acc[i][3] + bias.w;
        *(float4*)&g_xp[((size_t)ss * B_ + bb) * G4_ + n0 + tn * 4] = v;
    }
}

// =====================================================================
// k2: persistent LSTM. 128 CTAs = 16 batch-groups x 8 hidden-groups.
// CTA: 8 batches x 32 hidden units (128 gate rows). W_hh slice in SMEM.
// =====================================================================
#define K2_SMEM (64*128*16 + 8*67*16 + 128*9*4)   // 144256 B

__device__ __forceinline__ float sigmoidf_(float v) {
    return 1.f / (1.f + __expf(-v));
}

__global__ __launch_bounds__(256) void k2_lstm(const float* __restrict__ W_hh)
{
    extern __shared__ __align__(16) float sm2[];
    float4* w4 = (float4*)sm2;            // [64][128]  (k4-outer, gr-inner)
    float4* h4 = w4 + 64 * 128;           // [8][67]    (row pad 67 -> conflict-free)
    float*  gs = (float*)(h4 + 8 * 67);   // [128][9]   gate partial/final

    const int t   = threadIdx.x;
    const int bg  = blockIdx.x >> 3;      // 0..15
    const int hg  = blockIdx.x & 7;       // 0..7
    const int bb0 = bg * 8;
    const int h0  = hg * 32;

    // resident W_hh slice: gr = q*32+hi  ->  global row q*256 + h0 + hi
    for (int idx = t; idx < 128 * 64; idx += 256) {
        const int gr = idx >> 6, k4 = idx & 63;
        const int q = gr >> 5, hi = gr & 31;
        const int grow = q * 256 + h0 + hi;
        w4[k4 * 128 + gr] = ((const float4*)W_hh)[(size_t)grow * 64 + k4];
    }

    const int pb  = t >> 5, phi = t & 31;   // pointwise mapping (batch, hidden)
    const int gr  = t & 127, ks = t >> 7;   // gemm mapping (gate-row, k-split)
    float c_state = 0.f;

    __syncthreads();

    for (int s = 0; s < S_; ++s) {
        // prefetch this step's xp gates (consumed after GEMM; latency hidden)
        float xpv[4];
        {
            const float* xp = g_xp + ((size_t)s * B_ + (bb0 + pb)) * G4_ + h0 + phi;
            #pragma unroll
            for (int q = 0; q < 4; q++) xpv[q] = __ldcs(xp + q * 256);
        }

        if (s > 0) {
            // load h(s-1) for our 8 batches (L2 via .cg: cross-SM producer)
            const float4* hsrc = (const float4*)(g_h + ((size_t)(s - 1) * B_ + bb0) * H_);
            #pragma unroll
            for (int i = 0; i < 2; i++) {
                const int idx = t + i * 256;
                const int b = idx >> 6, k4 = idx & 63;
                h4[b * 67 + k4] = __ldcg(hsrc + b * 64 + k4);
            }
            __syncthreads();

            float acc[8];
            #pragma unroll
            for (int b = 0; b < 8; b++) acc[b] = 0.f;
            const float4* wp = w4 + ks * 32 * 128 + gr;
            const float4* hp = h4 + ks * 32;
            #pragma unroll 8
            for (int k4 = 0; k4 < 32; k4++) {
                const float4 w = wp[k4 * 128];
                #pragma unroll
                for (int b = 0; b < 8; b++) {
                    const float4 hv = hp[b * 67 + k4];
                    acc[b] = fmaf(w.x, hv.x, acc[b]);
                    acc[b] = fmaf(w.y, hv.y, acc[b]);
                    acc[b] = fmaf(w.z, hv.z, acc[b]);
                    acc[b] = fmaf(w.w, hv.w, acc[b]);
                }
            }
            if (ks == 1) {
                #pragma unroll
                for (int b = 0; b < 8; b++) gs[gr * 9 + b] = acc[b];
            }
            __syncthreads();
            if (ks == 0) {
                #pragma unroll
                for (int b = 0; b < 8; b++) gs[gr * 9 + b] += acc[b];
            }
            __syncthreads();
        }

        // pointwise gate math for (pb, phi)
        float gi = xpv[0], gf = xpv[1], gg = xpv[2], go = xpv[3];
        if (s > 0) {
            gi += gs[(0  + phi) * 9 + pb];
            gf += gs[(32 + phi) * 9 + pb];
            gg += gs[(64 + phi) * 9 + pb];
            go += gs[(96 + phi) * 9 + pb];
        }
        const float iv = sigmoidf_(gi);
        const float fv = sigmoidf_(gf);
        const float gv = tanhf(gg);
        const float ov = sigmoidf_(go);
        c_state = fv * c_state + iv * gv;
        const float hval = ov * tanhf(c_state);
        g_h[((size_t)s * B_ + (bb0 + pb)) * H_ + h0 + phi] = hval;

        // grid barrier (monotone, wrap-safe; release/acquire)
        __syncthreads();
        if (t == 0) {
            __threadfence();
            const unsigned old = atomicAdd(&g_bar, 1u);
            const unsigned target = (old & ~127u) + 128u;
            unsigned cur;
            do {
                asm volatile("ld.acquire.gpu.b32 %0, [%1];" : "=r"(cur) : "l"(&g_bar));
            } while ((int)(cur - target) < 0);
        }
        __syncthreads();
    }
}

// =====================================================================
// k3: scores[b][s] = sum_j tanh(h[b,s,:]·W1[j,:] + b1[j]) * U[j]
// 128 CTAs (one per batch). W1 resident in SMEM (k4-outer layout).
// =====================================================================
#define K3_SMEM (64*128*16 + 64*16 + 128*4 + 128*4 + 128*4 + 4*4)  // 133648 B

__global__ __launch_bounds__(256) void k3_scores(
    const float* __restrict__ W1, const float* __restrict__ b1,
    const float* __restrict__ U)
{
    extern __shared__ __align__(16) float sm3[];
    float4* w4   = (float4*)sm3;          // [64][128]
    float4* h4   = w4 + 64 * 128;         // [64]
    float*  u_s  = (float*)(h4 + 64);     // [128]
    float*  b1_s = u_s + 128;             // [128]
    float*  red  = b1_s + 128;            // [128]
    float*  wsum = red + 128;             // [4]

    const int t = threadIdx.x;
    const int b = blockIdx.x;

    for (int idx = t; idx < 128 * 64; idx += 256) {
        const int j = idx >> 6, k4 = idx & 63;
        w4[k4 * 128 + j] = ((const float4*)W1)[(size_t)j * 64 + k4];
    }
    if (t < 128) { u_s[t] = U[t]; b1_s[t] = b1[t]; }

    const int j = t & 127, ks = t >> 7;
    __syncthreads();

    for (int s = 0; s < S_; ++s) {
        const float4* hsrc = (const float4*)(g_h + ((size_t)s * B_ + b) * H_);
        if (t < 64) h4[t] = hsrc[t];
        __syncthreads();

        float acc = 0.f;
        const float4* wp = w4 + ks * 32 * 128 + j;
        const float4* hp = h4 + ks * 32;
        #pragma unroll 8
        for (int k4 = 0; k4 < 32; k4++) {
            const float4 w = wp[k4 * 128];
            const float4 hv = hp[k4];
            acc = fmaf(w.x, hv.x, acc);
            acc = fmaf(w.y, hv.y, acc);
            acc = fmaf(w.z, hv.z, acc);
            acc = fmaf(w.w, hv.w, acc);
        }
        if (ks == 1) red[j] = acc;
        __syncthreads();
        if (ks == 0) {
            const float aj = tanhf(acc + red[j] + b1_s[j]);
            float v = aj * u_s[j];
            #pragma unroll
            for (int o = 16; o; o >>= 1) v += __shfl_xor_sync(0xffffffffu, v, o);
            if ((t & 31) == 0) wsum[t >> 5] = v;
        }
        __syncthreads();
        if (t == 0) g_alpha[b * S_ + s] = wsum[0] + wsum[1] + wsum[2] + wsum[3];
        __syncthreads();
    }
}

// =====================================================================
// k4: softmax over s for each batch row (numerically stable)
// =====================================================================
__global__ __launch_bounds__(256) void k4_softmax()
{
    __shared__ float wr[8];
    const int t = threadIdx.x, b = blockIdx.x;
    float* row = g_alpha + b * S_;
    const float v0 = row[t], v1 = row[t + 256];

    float m = fmaxf(v0, v1);
    #pragma unroll
    for (int o = 16; o; o >>= 1) m = fmaxf(m, __shfl_xor_sync(0xffffffffu, m, o));
    if ((t & 31) == 0) wr[t >> 5] = m;
    __syncthreads();
    float mm = wr[0];
    #pragma unroll
    for (int i = 1; i < 8; i++) mm = fmaxf(mm, wr[i]);
    __syncthreads();

    const float e0 = __expf(v0 - mm), e1 = __expf(v1 - mm);
    float sum = e0 + e1;
    #pragma unroll
    for (int o = 16; o; o >>= 1) sum += __shfl_xor_sync(0xffffffffu, sum, o);
    if ((t & 31) == 0) wr[t >> 5] = sum;
    __syncthreads();
    float tot = 0.f;
    #pragma unroll
    for (int i = 0; i < 8; i++) tot += wr[i];
    const float inv = 1.f / tot;
    row[t] = e0 * inv;
    row[t + 256] = e1 * inv;
}

// =====================================================================
// k5: ctx[b,h] = sum_s alpha[b,s]*h[s,b,h]; logit = ctx @ W2^T + b2
// =====================================================================
__global__ __launch_bounds__(256) void k5_out(
    const float* __restrict__ W2, const float* __restrict__ b2,
    float* __restrict__ out)
{
    __shared__ float al[S_];
    __shared__ float wr[8];
    const int t = threadIdx.x, b = blockIdx.x;
    al[t]       = g_alpha[b * S_ + t];
    al[t + 256] = g_alpha[b * S_ + 256 + t];
    __syncthreads();

    const float* hp = g_h + (size_t)b * H_ + t;
    float acc = 0.f;
    #pragma unroll 4
    for (int s = 0; s < S_; s++)
        acc = fmaf(al[s], __ldg(hp + (size_t)s * (B_ * H_)), acc);

    #pragma unroll
    for (int c = 0; c < C_; c++) {
        float v = acc * W2[c * H_ + t];
        #pragma unroll
        for (int o = 16; o; o >>= 1) v += __shfl_xor_sync(0xffffffffu, v, o);
        if ((t & 31) == 0) wr[t >> 5] = v;
        __syncthreads();
        if (t == 0) {
            float sm_ = 0.f;
            #pragma unroll
            for (int i = 0; i < 8; i++) sm_ += wr[i];
            out[b * C_ + c] = sm_ + b2[c];
        }
        __syncthreads();
    }
}

// =====================================================================
extern "C" void kernel_launch(void* const* d_in, const int* in_sizes, int n_in,
                              void* d_out, int out_size)
{
    const int*   x    = (const int*)  d_in[0];
    const float* emb  = (const float*)d_in[1];
    const float* W_ih = (const float*)d_in[2];
    const float* W_hh = (const float*)d_in[3];
    const float* b_ih = (const float*)d_in[4];
    const float* b_hh = (const float*)d_in[5];
    const float* W1   = (const float*)d_in[6];
    const float* b1   = (const float*)d_in[7];
    const float* U    = (const float*)d_in[8];
    const float* W2   = (const float*)d_in[9];
    const float* b2   = (const float*)d_in[10];
    float* out = (float*)d_out;

    cudaFuncSetAttribute(k2_lstm,   cudaFuncAttributeMaxDynamicSharedMemorySize, K2_SMEM);
    cudaFuncSetAttribute(k3_scores, cudaFuncAttributeMaxDynamicSharedMemorySize, K3_SMEM);

    dim3 g1(G4_ / K1_BN, (B_ * S_) / K1_BM);   // 16 x 512
    k1_xproj <<<g1, 256>>>(x, emb, W_ih, b_ih, b_hh);
    k2_lstm  <<<128, 256, K2_SMEM>>>(W_hh);
    k3_scores<<<128, 256, K3_SMEM>>>(W1, b1, U);
    k4_softmax<<<128, 256>>>();
    k5_out   <<<128, 256>>>(W2, b2, out);
}